// round 15
// baseline (speedup 1.0000x reference)
#include <cuda_runtime.h>
#include <cuda_fp16.h>
#include <cstdint>
#include <cstddef>

// Problem dims (fixed by the dataset)
#define DIN   4096
#define DOUT  4096
#define MTOT  16384            // B*S = 4*4096
#define LORA_R 16
#define LORA_SCALE 2.0f        // alpha/r = 32/16

// ---------------------------------------------------------------------------
// Scratch: pre-converted fp16 copies (device globals; no allocation)
// ---------------------------------------------------------------------------
__device__ __half g_xh[(size_t)MTOT * DIN];
__device__ __half g_wh[(size_t)DOUT * DIN];

// ---------------------------------------------------------------------------
// Baseline-PTX helpers (no 'a'-suffix features: mma.sync / ldmatrix / cp.async)
// ---------------------------------------------------------------------------
__device__ __forceinline__ uint32_t smem_to_u32(const void* smem_ptr) {
    uint32_t addr;
    asm("{ .reg .u64 tmp; cvta.to.shared.u64 tmp, %1; cvt.u32.u64 %0, tmp; }"
        : "=r"(addr) : "l"(smem_ptr));
    return addr;
}

__device__ __forceinline__ void cp_async16(uint32_t dst, const void* src) {
    asm volatile("cp.async.cg.shared.global [%0], [%1], 16;"
                 :: "r"(dst), "l"(src));
}
__device__ __forceinline__ void cp_commit() {
    asm volatile("cp.async.commit_group;" ::: "memory");
}
template <int N>
__device__ __forceinline__ void cp_wait_group() {
    asm volatile("cp.async.wait_group %0;" :: "n"(N) : "memory");
}

__device__ __forceinline__ void ldsm4(uint32_t* r, uint32_t addr) {
    asm volatile("ldmatrix.sync.aligned.m8n8.x4.shared.b16 {%0,%1,%2,%3}, [%4];"
                 : "=r"(r[0]), "=r"(r[1]), "=r"(r[2]), "=r"(r[3]) : "r"(addr));
}

// D(16x8) += A(16x16,row) * B(8x16 stored [n][k] i.e. col-major KxN), f16->f32
__device__ __forceinline__ void mma_f16(float* c, const uint32_t* a, const uint32_t* b) {
    asm volatile(
        "mma.sync.aligned.m16n8k16.row.col.f32.f16.f16.f32 "
        "{%0,%1,%2,%3}, {%4,%5,%6,%7}, {%8,%9}, {%0,%1,%2,%3};"
        : "+f"(c[0]), "+f"(c[1]), "+f"(c[2]), "+f"(c[3])
        : "r"(a[0]), "r"(a[1]), "r"(a[2]), "r"(a[3]), "r"(b[0]), "r"(b[1]));
}

// ---------------------------------------------------------------------------
// Merged pre-pass: blocks [0, 65536) convert x -> fp16;
//                  blocks [65536, 131072) build W_eff -> fp16.
// ---------------------------------------------------------------------------
__global__ void prep_kernel(const float4* __restrict__ x4,
                            const float* __restrict__ W,
                            const float* __restrict__ lA,
                            const float* __restrict__ lB) {
    const int b = blockIdx.x;
    if (b < 65536) {
        size_t i = (size_t)b * 256 + threadIdx.x;
        float4 v = x4[i];
        __half2 p0 = __floats2half2_rn(v.x, v.y);
        __half2 p1 = __floats2half2_rn(v.z, v.w);
        uint2 o;
        o.x = *reinterpret_cast<uint32_t*>(&p0);
        o.y = *reinterpret_cast<uint32_t*>(&p1);
        reinterpret_cast<uint2*>(g_xh)[i] = o;
    } else {
        int idx = (b - 65536) * 256 + threadIdx.x;
        int n = idx >> 12;
        int k = idx & 4095;
        float acc = W[idx];                              // W is [DOUT, DIN]
        const float4* a4 = reinterpret_cast<const float4*>(lA + (size_t)k * LORA_R);
#pragma unroll
        for (int r4 = 0; r4 < 4; r4++) {
            float4 a = a4[r4];
            acc = fmaf(LORA_SCALE * a.x, __ldg(lB + (size_t)(r4 * 4 + 0) * DOUT + n), acc);
            acc = fmaf(LORA_SCALE * a.y, __ldg(lB + (size_t)(r4 * 4 + 1) * DOUT + n), acc);
            acc = fmaf(LORA_SCALE * a.z, __ldg(lB + (size_t)(r4 * 4 + 2) * DOUT + n), acc);
            acc = fmaf(LORA_SCALE * a.w, __ldg(lB + (size_t)(r4 * 4 + 3) * DOUT + n), acc);
        }
        g_wh[idx] = __float2half_rn(acc);
    }
}

// ---------------------------------------------------------------------------
// Main GEMM (Ampere-style, baseline PTX only):
//   CTA tile 128x128, BK=32, 4-stage cp.async ring (2-ahead prefetch),
//   256 threads / 8 warps as 2(M) x 4(N), warp tile 64x32, 2 CTAs/SM.
//   Inner loop explicitly software-pipelined:
//     - all 4 B fragments (both ks) batched up-front (MLP burst),
//     - A fragment double-buffered: ldsm A[i+1] issues before the 4 MMAs
//       consuming A[i], hiding the 29-cyc LDS latency under tensor work.
//   Single-term fp16 mma, fp32 accumulators.
// SMEM rows 80B-strided (64B data + 16B pad) -> conflict-free LDSM.
// ---------------------------------------------------------------------------
#define BM          128
#define BN          128
#define BK          32
#define ROW_STRIDE  80                         // 32 fp16 = 64B + 16B pad
#define A_TILE_BYTES (BM * ROW_STRIDE)         // 10240
#define B_TILE_BYTES (BN * ROW_STRIDE)         // 10240
#define OFF_B       A_TILE_BYTES
#define STAGE_BYTES (A_TILE_BYTES + B_TILE_BYTES)  // 20480
#define NSTAGE      4
#define SMEM_TOTAL  (NSTAGE * STAGE_BYTES)     // 81920 per CTA; x2 CTAs = 160KB/SM

__global__ void __launch_bounds__(256, 2)
lora_main_kernel(const float* __restrict__ bias, float* __restrict__ out)
{
    extern __shared__ char smem[];
    const uint32_t smem_base = smem_to_u32(smem);
    const int tid    = threadIdx.x;
    const int lane   = tid & 31;
    const int wid    = tid >> 5;
    const int warp_m = wid >> 2;             // 0..1 (64 rows each)
    const int warp_n = wid & 3;              // 0..3 (32 cols each)
    const int n0 = blockIdx.x * BN;          // N tile fastest -> W_eff L2-resident
    const int m0 = blockIdx.y * BM;

    // ---- cp.async slots: 2 chunks per tile per thread ---------------------
    const int row0 = tid >> 2;               // 0..63
    const int c0   = tid & 3;                // 16B chunk within 64B row
    const uint32_t so0 = (uint32_t)(row0 * ROW_STRIDE + c0 * 16);
    const uint32_t so1 = so0 + 64 * ROW_STRIDE;
    const char* pA = (const char*)g_xh + ((size_t)(m0 + row0) * DIN + c0 * 8) * 2;
    const char* pB = (const char*)g_wh + ((size_t)(n0 + row0) * DIN + c0 * 8) * 2;
    const size_t rstep = (size_t)64 * DIN * 2;   // +64 rows in gmem

    const int NCH = DIN / BK;                // 128 k-chunks

    auto issue_stage = [&](int s) {
        if (s < NCH) {
            const uint32_t sb = smem_base + (uint32_t)(s & (NSTAGE - 1)) * STAGE_BYTES;
            const size_t g = (size_t)s * (BK * 2);   // 64 bytes per k-chunk
            cp_async16(sb + so0,         pA + g);
            cp_async16(sb + so1,         pA + g + rstep);
            cp_async16(sb + OFF_B + so0, pB + g);
            cp_async16(sb + OFF_B + so1, pB + g + rstep);
        }
        cp_commit();                         // commit even when empty (group count)
    };

    // ---- ldmatrix address bases (per thread) ----------------------------
    // A (fragment order: row-blocks first, then k-halves):
    //   lanes 0-7->rows0-7@k0-7 | 8-15->rows8-15@k0-7 | 16-23->rows0-7@k8-15 | 24-31->rows8-15@k8-15
    const uint32_t a_off = (uint32_t)((warp_m * 64 + (lane & 15)) * ROW_STRIDE + (lane >> 4) * 16);
    // B (fragment order: k-halves first within an n-block — {b0,b1} =
    //  {B[n,k0-7], B[n,k8-15]} of the SAME n-block):
    const int b_row  = (lane & 7) + ((lane >> 4) << 3);
    const int b_koff = ((lane >> 3) & 1) * 16;
    const uint32_t b_off = (uint32_t)((warp_n * 32 + b_row) * ROW_STRIDE + b_koff);

    float acc[4][4][4];
#pragma unroll
    for (int i = 0; i < 4; i++)
#pragma unroll
        for (int j = 0; j < 4; j++)
#pragma unroll
            for (int e = 0; e < 4; e++) acc[i][j][e] = 0.0f;

    // Prologue: prefetch 3 stages (4-stage ring, up to 3 in flight)
    issue_stage(0); issue_stage(1); issue_stage(2);

    for (int ic = 0; ic < NCH; ++ic) {
        cp_wait_group<2>();                  // stage ic landed (2 more may fly)
        __syncthreads();                     // all warps done with buf (ic-1)%4
        issue_stage(ic + 3);                 // refill the freed buffer

        const uint32_t sb = smem_base + (uint32_t)(ic & (NSTAGE - 1)) * STAGE_BYTES;
        const uint32_t aA = sb + a_off;
        const uint32_t aB = sb + OFF_B + b_off;

        // ---- software-pipelined inner loop -------------------------------
        uint32_t B[2][2][4];                 // [ks][nb]
#pragma unroll
        for (int ks = 0; ks < 2; ks++)
#pragma unroll
            for (int nb = 0; nb < 2; nb++)
                ldsm4(B[ks][nb], aB + nb * (16 * ROW_STRIDE) + ks * 32);

        uint32_t A[2][4];                    // double-buffered A fragment
        ldsm4(A[0], aA);                     // i=0: ks0, mf0
#pragma unroll
        for (int i = 0; i < 8; i++) {        // i = ks*4 + mf
            const int ks = i >> 2, mf = i & 3;
            if (i < 7) {                     // prefetch A for step i+1
                const int ni = i + 1, nks = ni >> 2, nmf = ni & 3;
                ldsm4(A[ni & 1], aA + nmf * (16 * ROW_STRIDE) + nks * 32);
            }
#pragma unroll
            for (int nf = 0; nf < 4; nf++)
                mma_f16(acc[mf][nf], A[i & 1], &B[ks][nf >> 1][(nf & 1) * 2]);
        }
    }

    // ---- epilogue: D += bias, write fp32 --------------------------------
    const int row_base = m0 + warp_m * 64 + (lane >> 2);
    const int col_base = n0 + warp_n * 32 + (lane & 3) * 2;
    float bx[4][2];
#pragma unroll
    for (int nf = 0; nf < 4; nf++) {
        bx[nf][0] = bias[col_base + nf * 8];
        bx[nf][1] = bias[col_base + nf * 8 + 1];
    }
#pragma unroll
    for (int mf = 0; mf < 4; mf++) {
        float* p0 = out + (size_t)(row_base + mf * 16) * DOUT + col_base;
        float* p1 = p0 + 8 * DOUT;
#pragma unroll
        for (int nf = 0; nf < 4; nf++) {
            float2 v0, v1;
            v0.x = acc[mf][nf][0] + bx[nf][0];
            v0.y = acc[mf][nf][1] + bx[nf][1];
            v1.x = acc[mf][nf][2] + bx[nf][0];
            v1.y = acc[mf][nf][3] + bx[nf][1];
            *reinterpret_cast<float2*>(p0 + nf * 8) = v0;
            *reinterpret_cast<float2*>(p1 + nf * 8) = v1;
        }
    }
}

// ---------------------------------------------------------------------------
// kernel_launch: merged prep, then the GEMM. Graph-capturable; no allocs.
// ---------------------------------------------------------------------------
extern "C" void kernel_launch(void* const* d_in, const int* in_sizes, int n_in,
                              void* d_out, int out_size) {
    const float* x  = (const float*)d_in[0];   // [4,4096,4096]
    const float* W  = (const float*)d_in[1];   // [4096,4096]
    const float* b  = (const float*)d_in[2];   // [4096]
    const float* lA = (const float*)d_in[3];   // [4096,16]
    const float* lB = (const float*)d_in[4];   // [16,4096]
    float* out = (float*)d_out;

    prep_kernel<<<131072, 256>>>(reinterpret_cast<const float4*>(x), W, lA, lB);

    cudaFuncSetAttribute(lora_main_kernel,
                         cudaFuncAttributeMaxDynamicSharedMemorySize, SMEM_TOTAL);
    dim3 grid(DOUT / BN, MTOT / BM);   // (32, 128): N fastest for L2 reuse of W
    lora_main_kernel<<<grid, 256, SMEM_TOTAL>>>(b, out);
}

// round 16
// speedup vs baseline: 1.1219x; 1.1219x over previous
#include <cuda_runtime.h>
#include <cuda_fp16.h>
#include <cstdint>
#include <cstddef>

// Problem dims (fixed by the dataset)
#define DIN   4096
#define DOUT  4096
#define MTOT  16384            // B*S = 4*4096
#define LORA_R 16
#define LORA_SCALE 2.0f        // alpha/r = 32/16

// ---------------------------------------------------------------------------
// Scratch: pre-converted fp16 copies (device globals; no allocation)
// ---------------------------------------------------------------------------
__device__ __half g_xh[(size_t)MTOT * DIN];
__device__ __half g_wh[(size_t)DOUT * DIN];

// ---------------------------------------------------------------------------
// Baseline-PTX helpers (no 'a'-suffix features: mma.sync / ldmatrix / cp.async)
// ---------------------------------------------------------------------------
__device__ __forceinline__ uint32_t smem_to_u32(const void* smem_ptr) {
    uint32_t addr;
    asm("{ .reg .u64 tmp; cvta.to.shared.u64 tmp, %1; cvt.u32.u64 %0, tmp; }"
        : "=r"(addr) : "l"(smem_ptr));
    return addr;
}

__device__ __forceinline__ void cp_async16(uint32_t dst, const void* src) {
    asm volatile("cp.async.cg.shared.global [%0], [%1], 16;"
                 :: "r"(dst), "l"(src));
}
__device__ __forceinline__ void cp_commit() {
    asm volatile("cp.async.commit_group;" ::: "memory");
}
template <int N>
__device__ __forceinline__ void cp_wait_group() {
    asm volatile("cp.async.wait_group %0;" :: "n"(N) : "memory");
}

__device__ __forceinline__ void ldsm4(uint32_t* r, uint32_t addr) {
    asm volatile("ldmatrix.sync.aligned.m8n8.x4.shared.b16 {%0,%1,%2,%3}, [%4];"
                 : "=r"(r[0]), "=r"(r[1]), "=r"(r[2]), "=r"(r[3]) : "r"(addr));
}

// D(16x8) += A(16x16,row) * B(8x16 stored [n][k] i.e. col-major KxN), f16->f32
__device__ __forceinline__ void mma_f16(float* c, const uint32_t* a, const uint32_t* b) {
    asm volatile(
        "mma.sync.aligned.m16n8k16.row.col.f32.f16.f16.f32 "
        "{%0,%1,%2,%3}, {%4,%5,%6,%7}, {%8,%9}, {%0,%1,%2,%3};"
        : "+f"(c[0]), "+f"(c[1]), "+f"(c[2]), "+f"(c[3])
        : "r"(a[0]), "r"(a[1]), "r"(a[2]), "r"(a[3]), "r"(b[0]), "r"(b[1]));
}

// ---------------------------------------------------------------------------
// Merged pre-pass:
//   blocks [0, 65536): convert x -> fp16 (DRAM-bound).
//   blocks [65536, 69632): build W_eff -> fp16, smem-tiled (L2/LDS-bound).
// The two phases use disjoint resources and overlap in one launch.
// W-part: each block does an 8n x 512k tile. lA slice (32KB) is staged in
// smem TRANSPOSED ([r][k]) so compute LDS.128 reads are lane-consecutive
// (conflict-free). Per output: 1 coalesced W read + 16 smem FMA + 8B store.
// Math is order-identical to previous rounds (r ascending, x2 exact)
// -> g_wh bit-identical -> rel_err must stay 2.9349e-4.
// ---------------------------------------------------------------------------
__global__ void prep_kernel(const float4* __restrict__ x4,
                            const float* __restrict__ W,
                            const float* __restrict__ lA,
                            const float* __restrict__ lB) {
    __shared__ float lA_sT[16][512];     // 32KB, transposed lA slice
    __shared__ float lB_s[8][16];        // 8 n-values x 16 ranks
    const int b = blockIdx.x;
    const int tid = threadIdx.x;

    if (b < 65536) {
        // ---- x conversion: 1 float4 per thread ---------------------------
        size_t i = (size_t)b * 256 + tid;
        float4 v = x4[i];
        __half2 p0 = __floats2half2_rn(v.x, v.y);
        __half2 p1 = __floats2half2_rn(v.z, v.w);
        uint2 o;
        o.x = *reinterpret_cast<uint32_t*>(&p0);
        o.y = *reinterpret_cast<uint32_t*>(&p1);
        reinterpret_cast<uint2*>(g_xh)[i] = o;
        return;
    }

    // ---- W_eff tile: 8 n-rows x 512 k ------------------------------------
    const int wb = b - 65536;            // 0..4095
    const int n0 = (wb >> 3) * 8;        // n-group
    const int k0 = (wb & 7) * 512;       // k-group

    // Stage lA[k0..k0+511][0..15] into smem transposed (32KB contiguous read)
    const float4* lA4 = reinterpret_cast<const float4*>(lA + (size_t)k0 * LORA_R);
#pragma unroll
    for (int jj = 0; jj < 8; jj++) {
        int i = tid + jj * 256;          // 0..2047 float4s
        float4 v = lA4[i];
        int k  = i >> 2;
        int r0 = (i & 3) * 4;
        lA_sT[r0 + 0][k] = v.x;
        lA_sT[r0 + 1][k] = v.y;
        lA_sT[r0 + 2][k] = v.z;
        lA_sT[r0 + 3][k] = v.w;
    }
    if (tid < 128) {
        int nl = tid >> 4, r = tid & 15;
        lB_s[nl][r] = lB[(size_t)r * DOUT + n0 + nl];
    }
    __syncthreads();

    const int nl   = tid >> 5;           // warp -> n-row (8 warps, 8 rows)
    const int lane = tid & 31;
    float lBr[16];
#pragma unroll
    for (int r = 0; r < 16; r++) lBr[r] = LORA_SCALE * lB_s[nl][r];

    const float4* Wrow = reinterpret_cast<const float4*>(
        W + (size_t)(n0 + nl) * DIN + k0);
    __half* dst = g_wh + (size_t)(n0 + nl) * DIN + k0;

#pragma unroll
    for (int j = 0; j < 4; j++) {
        const int kk = lane * 4 + j * 128;   // 4 consecutive k per lane
        float4 w4 = Wrow[kk >> 2];           // coalesced 128B per warp phase
        float o0 = w4.x, o1 = w4.y, o2 = w4.z, o3 = w4.w;
#pragma unroll
        for (int r = 0; r < 16; r++) {
            const float4 a = *reinterpret_cast<const float4*>(&lA_sT[r][kk]);
            o0 = fmaf(lBr[r], a.x, o0);
            o1 = fmaf(lBr[r], a.y, o1);
            o2 = fmaf(lBr[r], a.z, o2);
            o3 = fmaf(lBr[r], a.w, o3);
        }
        __half2 h0 = __floats2half2_rn(o0, o1);
        __half2 h1 = __floats2half2_rn(o2, o3);
        uint2 st;
        st.x = *reinterpret_cast<uint32_t*>(&h0);
        st.y = *reinterpret_cast<uint32_t*>(&h1);
        *reinterpret_cast<uint2*>(dst + kk) = st;   // 8B coalesced store
    }
}

// ---------------------------------------------------------------------------
// Main GEMM (Ampere-style, baseline PTX only) — R14 configuration, frozen:
//   CTA tile 128x128, BK=32, 4-stage cp.async ring (2-ahead prefetch),
//   256 threads / 8 warps as 2(M) x 4(N), warp tile 64x32, 2 CTAs/SM,
//   single-term fp16 mma, fp32 accumulators.
// SMEM rows 80B-strided (64B data + 16B pad) -> conflict-free LDSM.
// ---------------------------------------------------------------------------
#define BM          128
#define BN          128
#define BK          32
#define ROW_STRIDE  80                         // 32 fp16 = 64B + 16B pad
#define A_TILE_BYTES (BM * ROW_STRIDE)         // 10240
#define B_TILE_BYTES (BN * ROW_STRIDE)         // 10240
#define OFF_B       A_TILE_BYTES
#define STAGE_BYTES (A_TILE_BYTES + B_TILE_BYTES)  // 20480
#define NSTAGE      4
#define SMEM_TOTAL  (NSTAGE * STAGE_BYTES)     // 81920 per CTA; x2 CTAs = 160KB/SM

__global__ void __launch_bounds__(256, 2)
lora_main_kernel(const float* __restrict__ bias, float* __restrict__ out)
{
    extern __shared__ char smem[];
    const uint32_t smem_base = smem_to_u32(smem);
    const int tid    = threadIdx.x;
    const int lane   = tid & 31;
    const int wid    = tid >> 5;
    const int warp_m = wid >> 2;             // 0..1 (64 rows each)
    const int warp_n = wid & 3;              // 0..3 (32 cols each)
    const int n0 = blockIdx.x * BN;          // N tile fastest -> W_eff L2-resident
    const int m0 = blockIdx.y * BM;

    // ---- cp.async slots: 2 chunks per tile per thread ---------------------
    const int row0 = tid >> 2;               // 0..63
    const int c0   = tid & 3;                // 16B chunk within 64B row
    const uint32_t so0 = (uint32_t)(row0 * ROW_STRIDE + c0 * 16);
    const uint32_t so1 = so0 + 64 * ROW_STRIDE;
    const char* pA = (const char*)g_xh + ((size_t)(m0 + row0) * DIN + c0 * 8) * 2;
    const char* pB = (const char*)g_wh + ((size_t)(n0 + row0) * DIN + c0 * 8) * 2;
    const size_t rstep = (size_t)64 * DIN * 2;   // +64 rows in gmem

    const int NCH = DIN / BK;                // 128 k-chunks

    auto issue_stage = [&](int s) {
        if (s < NCH) {
            const uint32_t sb = smem_base + (uint32_t)(s & (NSTAGE - 1)) * STAGE_BYTES;
            const size_t g = (size_t)s * (BK * 2);   // 64 bytes per k-chunk
            cp_async16(sb + so0,         pA + g);
            cp_async16(sb + so1,         pA + g + rstep);
            cp_async16(sb + OFF_B + so0, pB + g);
            cp_async16(sb + OFF_B + so1, pB + g + rstep);
        }
        cp_commit();                         // commit even when empty (group count)
    };

    // ---- ldmatrix address bases (per thread) ----------------------------
    // A (fragment order: row-blocks first, then k-halves):
    //   lanes 0-7->rows0-7@k0-7 | 8-15->rows8-15@k0-7 | 16-23->rows0-7@k8-15 | 24-31->rows8-15@k8-15
    const uint32_t a_off = (uint32_t)((warp_m * 64 + (lane & 15)) * ROW_STRIDE + (lane >> 4) * 16);
    // B (fragment order: k-halves first within an n-block — {b0,b1} =
    //  {B[n,k0-7], B[n,k8-15]} of the SAME n-block):
    const int b_row  = (lane & 7) + ((lane >> 4) << 3);
    const int b_koff = ((lane >> 3) & 1) * 16;
    const uint32_t b_off = (uint32_t)((warp_n * 32 + b_row) * ROW_STRIDE + b_koff);

    float acc[4][4][4];
#pragma unroll
    for (int i = 0; i < 4; i++)
#pragma unroll
        for (int j = 0; j < 4; j++)
#pragma unroll
            for (int e = 0; e < 4; e++) acc[i][j][e] = 0.0f;

    // Prologue: prefetch 3 stages (4-stage ring, up to 3 in flight)
    issue_stage(0); issue_stage(1); issue_stage(2);

    for (int ic = 0; ic < NCH; ++ic) {
        cp_wait_group<2>();                  // stage ic landed (2 more may fly)
        __syncthreads();                     // all warps done with buf (ic-1)%4
        issue_stage(ic + 3);                 // refill the freed buffer

        const uint32_t sb = smem_base + (uint32_t)(ic & (NSTAGE - 1)) * STAGE_BYTES;
        const uint32_t aA = sb + a_off;
        const uint32_t aB = sb + OFF_B + b_off;
#pragma unroll
        for (int ks = 0; ks < 2; ks++) {
            uint32_t B[2][4];
#pragma unroll
            for (int nb = 0; nb < 2; nb++)
                ldsm4(B[nb], aB + nb * (16 * ROW_STRIDE) + ks * 32);
#pragma unroll
            for (int mf = 0; mf < 4; mf++) {
                uint32_t A[4];
                ldsm4(A, aA + mf * (16 * ROW_STRIDE) + ks * 32);
#pragma unroll
                for (int nf = 0; nf < 4; nf++)
                    mma_f16(acc[mf][nf], A, &B[nf >> 1][(nf & 1) * 2]);
            }
        }
    }

    // ---- epilogue: D += bias, write fp32 --------------------------------
    const int row_base = m0 + warp_m * 64 + (lane >> 2);
    const int col_base = n0 + warp_n * 32 + (lane & 3) * 2;
    float bx[4][2];
#pragma unroll
    for (int nf = 0; nf < 4; nf++) {
        bx[nf][0] = bias[col_base + nf * 8];
        bx[nf][1] = bias[col_base + nf * 8 + 1];
    }
#pragma unroll
    for (int mf = 0; mf < 4; mf++) {
        float* p0 = out + (size_t)(row_base + mf * 16) * DOUT + col_base;
        float* p1 = p0 + 8 * DOUT;
#pragma unroll
        for (int nf = 0; nf < 4; nf++) {
            float2 v0, v1;
            v0.x = acc[mf][nf][0] + bx[nf][0];
            v0.y = acc[mf][nf][1] + bx[nf][1];
            v1.x = acc[mf][nf][2] + bx[nf][0];
            v1.y = acc[mf][nf][3] + bx[nf][1];
            *reinterpret_cast<float2*>(p0 + nf * 8) = v0;
            *reinterpret_cast<float2*>(p1 + nf * 8) = v1;
        }
    }
}

// ---------------------------------------------------------------------------
// kernel_launch: merged prep, then the GEMM. Graph-capturable; no allocs.
// ---------------------------------------------------------------------------
extern "C" void kernel_launch(void* const* d_in, const int* in_sizes, int n_in,
                              void* d_out, int out_size) {
    const float* x  = (const float*)d_in[0];   // [4,4096,4096]
    const float* W  = (const float*)d_in[1];   // [4096,4096]
    const float* b  = (const float*)d_in[2];   // [4096]
    const float* lA = (const float*)d_in[3];   // [4096,16]
    const float* lB = (const float*)d_in[4];   // [16,4096]
    float* out = (float*)d_out;

    prep_kernel<<<65536 + 4096, 256>>>(reinterpret_cast<const float4*>(x),
                                       W, lA, lB);

    cudaFuncSetAttribute(lora_main_kernel,
                         cudaFuncAttributeMaxDynamicSharedMemorySize, SMEM_TOTAL);
    dim3 grid(DOUT / BN, MTOT / BM);   // (32, 128): N fastest for L2 reuse of W
    lora_main_kernel<<<grid, 256, SMEM_TOTAL>>>(b, out);
}

// round 17
// speedup vs baseline: 1.1407x; 1.0167x over previous
#include <cuda_runtime.h>
#include <cuda_fp16.h>
#include <cstdint>
#include <cstddef>

// Problem dims (fixed by the dataset)
#define DIN   4096
#define DOUT  4096
#define MTOT  16384            // B*S = 4*4096
#define LORA_R 16
#define LORA_SCALE 2.0f        // alpha/r = 32/16

// ---------------------------------------------------------------------------
// Scratch: pre-converted fp16 copies (device globals; no allocation)
// ---------------------------------------------------------------------------
__device__ __half g_xh[(size_t)MTOT * DIN];
__device__ __half g_wh[(size_t)DOUT * DIN];

// ---------------------------------------------------------------------------
// Baseline-PTX helpers (no 'a'-suffix features: mma.sync / ldmatrix / cp.async)
// ---------------------------------------------------------------------------
__device__ __forceinline__ uint32_t smem_to_u32(const void* smem_ptr) {
    uint32_t addr;
    asm("{ .reg .u64 tmp; cvta.to.shared.u64 tmp, %1; cvt.u32.u64 %0, tmp; }"
        : "=r"(addr) : "l"(smem_ptr));
    return addr;
}

__device__ __forceinline__ void cp_async16(uint32_t dst, const void* src) {
    asm volatile("cp.async.cg.shared.global [%0], [%1], 16;"
                 :: "r"(dst), "l"(src));
}
__device__ __forceinline__ void cp_commit() {
    asm volatile("cp.async.commit_group;" ::: "memory");
}
template <int N>
__device__ __forceinline__ void cp_wait_group() {
    asm volatile("cp.async.wait_group %0;" :: "n"(N) : "memory");
}

__device__ __forceinline__ void ldsm4(uint32_t* r, uint32_t addr) {
    asm volatile("ldmatrix.sync.aligned.m8n8.x4.shared.b16 {%0,%1,%2,%3}, [%4];"
                 : "=r"(r[0]), "=r"(r[1]), "=r"(r[2]), "=r"(r[3]) : "r"(addr));
}

// D(16x8) += A(16x16,row) * B(8x16 stored [n][k] i.e. col-major KxN), f16->f32
__device__ __forceinline__ void mma_f16(float* c, const uint32_t* a, const uint32_t* b) {
    asm volatile(
        "mma.sync.aligned.m16n8k16.row.col.f32.f16.f16.f32 "
        "{%0,%1,%2,%3}, {%4,%5,%6,%7}, {%8,%9}, {%0,%1,%2,%3};"
        : "+f"(c[0]), "+f"(c[1]), "+f"(c[2]), "+f"(c[3])
        : "r"(a[0]), "r"(a[1]), "r"(a[2]), "r"(a[3]), "r"(b[0]), "r"(b[1]));
}

// ---------------------------------------------------------------------------
// Merged pre-pass — W-blocks FIRST so the heavy L2/FMA-bound W_eff work
// launches immediately and overlaps with the DRAM-bound x-stream:
//   blocks [0, 4096):      build W_eff -> fp16, smem-tiled.
//   blocks [4096, 36864):  convert x -> fp16, 2 float4 per thread,
//                          single 16B store.
// W-part: each block does an 8n x 512k tile. lA slice (32KB) staged in smem
// TRANSPOSED ([r][k]) so compute LDS.128 reads are lane-consecutive.
// Math is order-identical to previous rounds -> g_wh/g_xh bit-identical
// -> rel_err must stay 2.9349e-4.
// ---------------------------------------------------------------------------
__global__ void prep_kernel(const float4* __restrict__ x4,
                            const float* __restrict__ W,
                            const float* __restrict__ lA,
                            const float* __restrict__ lB) {
    __shared__ float lA_sT[16][512];     // 32KB, transposed lA slice
    __shared__ float lB_s[8][16];        // 8 n-values x 16 ranks
    const int b = blockIdx.x;
    const int tid = threadIdx.x;

    if (b >= 4096) {
        // ---- x conversion: 2 consecutive float4 -> 1 uint4 store --------
        size_t i = (size_t)(b - 4096) * 256 + tid;   // 0 .. 8388607
        float4 v0 = x4[2 * i];
        float4 v1 = x4[2 * i + 1];
        __half2 p0 = __floats2half2_rn(v0.x, v0.y);
        __half2 p1 = __floats2half2_rn(v0.z, v0.w);
        __half2 p2 = __floats2half2_rn(v1.x, v1.y);
        __half2 p3 = __floats2half2_rn(v1.z, v1.w);
        uint4 o;
        o.x = *reinterpret_cast<uint32_t*>(&p0);
        o.y = *reinterpret_cast<uint32_t*>(&p1);
        o.z = *reinterpret_cast<uint32_t*>(&p2);
        o.w = *reinterpret_cast<uint32_t*>(&p3);
        reinterpret_cast<uint4*>(g_xh)[i] = o;
        return;
    }

    // ---- W_eff tile: 8 n-rows x 512 k ------------------------------------
    const int wb = b;                    // 0..4095
    const int n0 = (wb >> 3) * 8;        // n-group
    const int k0 = (wb & 7) * 512;       // k-group

    // Stage lA[k0..k0+511][0..15] into smem transposed (32KB contiguous read)
    const float4* lA4 = reinterpret_cast<const float4*>(lA + (size_t)k0 * LORA_R);
#pragma unroll
    for (int jj = 0; jj < 8; jj++) {
        int i = tid + jj * 256;          // 0..2047 float4s
        float4 v = lA4[i];
        int k  = i >> 2;
        int r0 = (i & 3) * 4;
        lA_sT[r0 + 0][k] = v.x;
        lA_sT[r0 + 1][k] = v.y;
        lA_sT[r0 + 2][k] = v.z;
        lA_sT[r0 + 3][k] = v.w;
    }
    if (tid < 128) {
        int nl = tid >> 4, r = tid & 15;
        lB_s[nl][r] = lB[(size_t)r * DOUT + n0 + nl];
    }
    __syncthreads();

    const int nl   = tid >> 5;           // warp -> n-row (8 warps, 8 rows)
    const int lane = tid & 31;
    float lBr[16];
#pragma unroll
    for (int r = 0; r < 16; r++) lBr[r] = LORA_SCALE * lB_s[nl][r];

    const float4* Wrow = reinterpret_cast<const float4*>(
        W + (size_t)(n0 + nl) * DIN + k0);
    __half* dst = g_wh + (size_t)(n0 + nl) * DIN + k0;

#pragma unroll
    for (int j = 0; j < 4; j++) {
        const int kk = lane * 4 + j * 128;   // 4 consecutive k per lane
        float4 w4 = Wrow[kk >> 2];           // coalesced 128B per warp phase
        float o0 = w4.x, o1 = w4.y, o2 = w4.z, o3 = w4.w;
#pragma unroll
        for (int r = 0; r < 16; r++) {
            const float4 a = *reinterpret_cast<const float4*>(&lA_sT[r][kk]);
            o0 = fmaf(lBr[r], a.x, o0);
            o1 = fmaf(lBr[r], a.y, o1);
            o2 = fmaf(lBr[r], a.z, o2);
            o3 = fmaf(lBr[r], a.w, o3);
        }
        __half2 h0 = __floats2half2_rn(o0, o1);
        __half2 h1 = __floats2half2_rn(o2, o3);
        uint2 st;
        st.x = *reinterpret_cast<uint32_t*>(&h0);
        st.y = *reinterpret_cast<uint32_t*>(&h1);
        *reinterpret_cast<uint2*>(dst + kk) = st;   // 8B coalesced store
    }
}

// ---------------------------------------------------------------------------
// Main GEMM (Ampere-style, baseline PTX only) — R14/R16 configuration, FROZEN:
//   CTA tile 128x128, BK=32, 4-stage cp.async ring (2-ahead prefetch),
//   256 threads / 8 warps as 2(M) x 4(N), warp tile 64x32, 2 CTAs/SM,
//   single-term fp16 mma, fp32 accumulators.
// SMEM rows 80B-strided (64B data + 16B pad) -> conflict-free LDSM.
// ---------------------------------------------------------------------------
#define BM          128
#define BN          128
#define BK          32
#define ROW_STRIDE  80                         // 32 fp16 = 64B + 16B pad
#define A_TILE_BYTES (BM * ROW_STRIDE)         // 10240
#define B_TILE_BYTES (BN * ROW_STRIDE)         // 10240
#define OFF_B       A_TILE_BYTES
#define STAGE_BYTES (A_TILE_BYTES + B_TILE_BYTES)  // 20480
#define NSTAGE      4
#define SMEM_TOTAL  (NSTAGE * STAGE_BYTES)     // 81920 per CTA; x2 CTAs = 160KB/SM

__global__ void __launch_bounds__(256, 2)
lora_main_kernel(const float* __restrict__ bias, float* __restrict__ out)
{
    extern __shared__ char smem[];
    const uint32_t smem_base = smem_to_u32(smem);
    const int tid    = threadIdx.x;
    const int lane   = tid & 31;
    const int wid    = tid >> 5;
    const int warp_m = wid >> 2;             // 0..1 (64 rows each)
    const int warp_n = wid & 3;              // 0..3 (32 cols each)
    const int n0 = blockIdx.x * BN;          // N tile fastest -> W_eff L2-resident
    const int m0 = blockIdx.y * BM;

    // ---- cp.async slots: 2 chunks per tile per thread ---------------------
    const int row0 = tid >> 2;               // 0..63
    const int c0   = tid & 3;                // 16B chunk within 64B row
    const uint32_t so0 = (uint32_t)(row0 * ROW_STRIDE + c0 * 16);
    const uint32_t so1 = so0 + 64 * ROW_STRIDE;
    const char* pA = (const char*)g_xh + ((size_t)(m0 + row0) * DIN + c0 * 8) * 2;
    const char* pB = (const char*)g_wh + ((size_t)(n0 + row0) * DIN + c0 * 8) * 2;
    const size_t rstep = (size_t)64 * DIN * 2;   // +64 rows in gmem

    const int NCH = DIN / BK;                // 128 k-chunks

    auto issue_stage = [&](int s) {
        if (s < NCH) {
            const uint32_t sb = smem_base + (uint32_t)(s & (NSTAGE - 1)) * STAGE_BYTES;
            const size_t g = (size_t)s * (BK * 2);   // 64 bytes per k-chunk
            cp_async16(sb + so0,         pA + g);
            cp_async16(sb + so1,         pA + g + rstep);
            cp_async16(sb + OFF_B + so0, pB + g);
            cp_async16(sb + OFF_B + so1, pB + g + rstep);
        }
        cp_commit();                         // commit even when empty (group count)
    };

    // ---- ldmatrix address bases (per thread) ----------------------------
    // A (fragment order: row-blocks first, then k-halves):
    //   lanes 0-7->rows0-7@k0-7 | 8-15->rows8-15@k0-7 | 16-23->rows0-7@k8-15 | 24-31->rows8-15@k8-15
    const uint32_t a_off = (uint32_t)((warp_m * 64 + (lane & 15)) * ROW_STRIDE + (lane >> 4) * 16);
    // B (fragment order: k-halves first within an n-block — {b0,b1} =
    //  {B[n,k0-7], B[n,k8-15]} of the SAME n-block):
    const int b_row  = (lane & 7) + ((lane >> 4) << 3);
    const int b_koff = ((lane >> 3) & 1) * 16;
    const uint32_t b_off = (uint32_t)((warp_n * 32 + b_row) * ROW_STRIDE + b_koff);

    float acc[4][4][4];
#pragma unroll
    for (int i = 0; i < 4; i++)
#pragma unroll
        for (int j = 0; j < 4; j++)
#pragma unroll
            for (int e = 0; e < 4; e++) acc[i][j][e] = 0.0f;

    // Prologue: prefetch 3 stages (4-stage ring, up to 3 in flight)
    issue_stage(0); issue_stage(1); issue_stage(2);

    for (int ic = 0; ic < NCH; ++ic) {
        cp_wait_group<2>();                  // stage ic landed (2 more may fly)
        __syncthreads();                     // all warps done with buf (ic-1)%4
        issue_stage(ic + 3);                 // refill the freed buffer

        const uint32_t sb = smem_base + (uint32_t)(ic & (NSTAGE - 1)) * STAGE_BYTES;
        const uint32_t aA = sb + a_off;
        const uint32_t aB = sb + OFF_B + b_off;
#pragma unroll
        for (int ks = 0; ks < 2; ks++) {
            uint32_t B[2][4];
#pragma unroll
            for (int nb = 0; nb < 2; nb++)
                ldsm4(B[nb], aB + nb * (16 * ROW_STRIDE) + ks * 32);
#pragma unroll
            for (int mf = 0; mf < 4; mf++) {
                uint32_t A[4];
                ldsm4(A, aA + mf * (16 * ROW_STRIDE) + ks * 32);
#pragma unroll
                for (int nf = 0; nf < 4; nf++)
                    mma_f16(acc[mf][nf], A, &B[nf >> 1][(nf & 1) * 2]);
            }
        }
    }

    // ---- epilogue: D += bias, write fp32 --------------------------------
    const int row_base = m0 + warp_m * 64 + (lane >> 2);
    const int col_base = n0 + warp_n * 32 + (lane & 3) * 2;
    float bx[4][2];
#pragma unroll
    for (int nf = 0; nf < 4; nf++) {
        bx[nf][0] = bias[col_base + nf * 8];
        bx[nf][1] = bias[col_base + nf * 8 + 1];
    }
#pragma unroll
    for (int mf = 0; mf < 4; mf++) {
        float* p0 = out + (size_t)(row_base + mf * 16) * DOUT + col_base;
        float* p1 = p0 + 8 * DOUT;
#pragma unroll
        for (int nf = 0; nf < 4; nf++) {
            float2 v0, v1;
            v0.x = acc[mf][nf][0] + bx[nf][0];
            v0.y = acc[mf][nf][1] + bx[nf][1];
            v1.x = acc[mf][nf][2] + bx[nf][0];
            v1.y = acc[mf][nf][3] + bx[nf][1];
            *reinterpret_cast<float2*>(p0 + nf * 8) = v0;
            *reinterpret_cast<float2*>(p1 + nf * 8) = v1;
        }
    }
}

// ---------------------------------------------------------------------------
// kernel_launch: merged prep (W-blocks first), then the GEMM.
// Graph-capturable; no allocs.
// ---------------------------------------------------------------------------
extern "C" void kernel_launch(void* const* d_in, const int* in_sizes, int n_in,
                              void* d_out, int out_size) {
    const float* x  = (const float*)d_in[0];   // [4,4096,4096]
    const float* W  = (const float*)d_in[1];   // [4096,4096]
    const float* b  = (const float*)d_in[2];   // [4096]
    const float* lA = (const float*)d_in[3];   // [4096,16]
    const float* lB = (const float*)d_in[4];   // [16,4096]
    float* out = (float*)d_out;

    prep_kernel<<<4096 + 32768, 256>>>(reinterpret_cast<const float4*>(x),
                                       W, lA, lB);

    cudaFuncSetAttribute(lora_main_kernel,
                         cudaFuncAttributeMaxDynamicSharedMemorySize, SMEM_TOTAL);
    dim3 grid(DOUT / BN, MTOT / BM);   // (32, 128): N fastest for L2 reuse of W
    lora_main_kernel<<<grid, 256, SMEM_TOTAL>>>(b, out);
}